// round 5
// baseline (speedup 1.0000x reference)
#include <cuda_runtime.h>
#include <cuda_fp16.h>

// CRF forward (log-partition) minus gold-path score.
//
// Reformulation:
//   alpha_t[j] = logsumexp_i(alpha_{t-1}[i] + T[j,i]) + feat_t[j]
// In exp domain with E = exp(T) (precomputed once, fp16):
//   u_t = diag(exp(feat_t)) * (E @ u_{t-1}),  log_Z = sum_t log(s_t) + lse(feat_0)
// where s_t is the per-step sum used for renormalization (telescoping).
//
// Parallelization: the per-step log-growth depends only on the *direction* of
// u, and the positive matrix E contracts directions (Hilbert metric) by
// ~0.06/step; diag(exp(feat)) factors are Hilbert isometries. So the sequence
// is split into NCHUNK independent chunks, each started from a uniform vector
// with BURN warm-up steps (contraction < 1e-9 even pessimistically), then
// accumulating log(s_t) over its owned step range. No inter-CTA sync in the
// hot loop. Chunk 0 starts from the exact u_0 = exp(feat_0).

#define LNUM     512
#define NCHUNK   296
#define BURN     32
#define NTHREADS 512

// Device scratch (static: no allocation allowed).
__device__ uint4 g_Ep4[(LNUM * LNUM) / 8];   // exp(T) fp16, packed [i>>3][j][i&7]
__device__ float g_acc[NCHUNK];
__device__ float g_gold;

// ---------------------------------------------------------------------------
// Prep: E = exp(T), fp16, transposed+packed so the matvec inner loop does one
// coalesced LDG.128 per 8 i-values per thread (thread j owns output j).
// Layout: half element index = (i>>3)*(LNUM*8) + j*8 + (i&7).
// ---------------------------------------------------------------------------
__global__ void prep_kernel(const float* __restrict__ T) {
    int idx = blockIdx.x * blockDim.x + threadIdx.x;   // idx = j*LNUM + i
    if (idx >= LNUM * LNUM) return;
    int j = idx >> 9;
    int i = idx & (LNUM - 1);
    float e = expf(T[idx]);                            // T[j,i], range ~[0.01, 90]
    __half* ep = reinterpret_cast<__half*>(g_Ep4);
    ep[(i >> 3) * (LNUM * 8) + j * 8 + (i & 7)] = __float2half(e);
}

// ---------------------------------------------------------------------------
// Reductions (fixed tree order -> deterministic).
// ---------------------------------------------------------------------------
__device__ __forceinline__ float warpSum(float x) {
#pragma unroll
    for (int o = 16; o; o >>= 1) x += __shfl_xor_sync(0xffffffffu, x, o);
    return x;
}
__device__ __forceinline__ float warpMax(float x) {
#pragma unroll
    for (int o = 16; o; o >>= 1) x = fmaxf(x, __shfl_xor_sync(0xffffffffu, x, o));
    return x;
}

// ---------------------------------------------------------------------------
// Main: one CTA = one chunk. 512 threads, thread j owns output row j.
// State vector v[512] lives in smem (broadcast LDS reads, conflict-free).
// ---------------------------------------------------------------------------
__global__ void __launch_bounds__(NTHREADS, 2)
chunk_kernel(const float* __restrict__ logit, int S, int K) {
    __shared__ __align__(16) float v[LNUM];
    __shared__ float red[16];
    __shared__ float sh_inv;
    __shared__ float sh_bcast;

    const int c    = blockIdx.x;
    const int j    = threadIdx.x;
    const int wid  = j >> 5;
    const int lane = j & 31;

    const int own_start = 1 + c * K;
    if (own_start >= S) { if (j == 0) g_acc[c] = 0.f; return; }
    int t_end = own_start + K;
    if (t_end > S) t_end = S;

    float acc = 0.f;   // only thread 0's copy is live
    int   t_begin;

    if (c == 0) {
        // Exact start: v = exp(feat_0 - m), acc = logsumexp(feat_0)
        float f = logit[j];
        float m = warpMax(f);
        if (lane == 0) red[wid] = m;
        __syncthreads();
        if (wid == 0) {
            float t = red[lane & 15];
            t = warpMax(t);
            if (lane == 0) sh_bcast = t;
        }
        __syncthreads();
        m = sh_bcast;
        float e = __expf(f - m);
        v[j] = e;
        float s = warpSum(e);
        if (lane == 0) red[wid] = s;
        __syncthreads();
        if (wid == 0) {
            float t = (lane < 16) ? red[lane] : 0.f;
            t = warpSum(t);
            if (lane == 0) { sh_inv = 1.f / t; acc = m + logf(t); }
        }
        __syncthreads();
        t_begin = 1;
    } else {
        // Uniform start + burn-in (not accumulated).
        v[j] = 1.f;
        if (j == 0) sh_inv = 1.f / (float)LNUM;
        __syncthreads();
        t_begin = own_start - BURN;
        if (t_begin < 1) t_begin = 1;
    }

    const uint4* __restrict__ ep = g_Ep4 + j;

    for (int t = t_begin; t < t_end; ++t) {
        const float inv = sh_inv;   // 1/sum of previous (unnormalized) v

        // y_j = sum_i E[j,i] * v[i]  — 512 fp16 weights, 64 LDG.128
        float y0 = 0.f, y1 = 0.f;
        const float4* v4 = reinterpret_cast<const float4*>(v);
#pragma unroll 8
        for (int blk = 0; blk < LNUM / 8; ++blk) {
            uint4 p  = ep[blk * LNUM];
            float4 va = v4[blk * 2];
            float4 vb = v4[blk * 2 + 1];
            float2 e0 = __half22float2(*reinterpret_cast<const __half2*>(&p.x));
            float2 e1 = __half22float2(*reinterpret_cast<const __half2*>(&p.y));
            float2 e2 = __half22float2(*reinterpret_cast<const __half2*>(&p.z));
            float2 e3 = __half22float2(*reinterpret_cast<const __half2*>(&p.w));
            y0 = fmaf(e0.x, va.x, y0); y1 = fmaf(e0.y, va.y, y1);
            y0 = fmaf(e1.x, va.z, y0); y1 = fmaf(e1.y, va.w, y1);
            y0 = fmaf(e2.x, vb.x, y0); y1 = fmaf(e2.y, vb.y, y1);
            y0 = fmaf(e3.x, vb.z, y0); y1 = fmaf(e3.y, vb.w, y1);
        }
        float y = (y0 + y1) * (inv * __expf(logit[t * LNUM + j]));

        __syncthreads();          // everyone done reading old v
        v[j] = y;                 // store new (unnormalized) state

        float s = warpSum(y);
        if (lane == 0) red[wid] = s;
        __syncthreads();
        if (wid == 0) {
            float ss = (lane < 16) ? red[lane] : 0.f;
            ss = warpSum(ss);
            if (lane == 0) {
                sh_inv = 1.f / ss;
                if (t >= own_start) acc += logf(ss);
            }
        }
        __syncthreads();
    }

    if (j == 0) g_acc[c] = acc;
}

// ---------------------------------------------------------------------------
// Gold path score: feat_0[y0] + sum_{t>0}(feat_t[y_t] + T[y_t, y_{t-1}])
// ---------------------------------------------------------------------------
__global__ void gold_kernel(const float* __restrict__ logit,
                            const int*   __restrict__ labels,
                            const float* __restrict__ T, int S) {
    __shared__ float red[16];
    int tid = threadIdx.x;
    float p = 0.f;
    for (int t = tid; t < S; t += NTHREADS) {
        int lt = labels[t];
        p += logit[t * LNUM + lt];
        if (t >= 1) p += T[lt * LNUM + labels[t - 1]];
    }
    float s = warpSum(p);
    if ((tid & 31) == 0) red[tid >> 5] = s;
    __syncthreads();
    if (tid < 32) {
        float ss = (tid < 16) ? red[tid] : 0.f;
        ss = warpSum(ss);
        if (tid == 0) g_gold = ss;
    }
}

// ---------------------------------------------------------------------------
// Final: deterministic fixed-order combine in double.
// ---------------------------------------------------------------------------
__global__ void final_kernel(float* __restrict__ out) {
    if (threadIdx.x == 0 && blockIdx.x == 0) {
        double s = 0.0;
        for (int c = 0; c < NCHUNK; ++c) s += (double)g_acc[c];
        out[0] = (float)(s - (double)g_gold);
    }
}

// ---------------------------------------------------------------------------
extern "C" void kernel_launch(void* const* d_in, const int* in_sizes, int n_in,
                              void* d_out, int out_size) {
    const float* logit  = (const float*)d_in[0];
    const int*   labels = (const int*)d_in[1];
    const float* T      = (const float*)d_in[2];
    const int S = in_sizes[1];                       // 32768
    const int K = (S - 1 + NCHUNK - 1) / NCHUNK;     // owned steps per chunk

    prep_kernel<<<(LNUM * LNUM + 255) / 256, 256>>>(T);
    gold_kernel<<<1, NTHREADS>>>(logit, labels, T, S);
    chunk_kernel<<<NCHUNK, NTHREADS>>>(logit, S, K);
    final_kernel<<<1, 32>>>((float*)d_out);
}

// round 6
// speedup vs baseline: 5.7026x; 5.7026x over previous
#include <cuda_runtime.h>

// CRF forward (log-partition) minus gold-path score — int8/dp4a edition.
//
// Exp-domain: u_t = diag(exp(feat_t)) * E * u_{t-1}, E = exp(T) precomputed.
// E quantized per-row to u8: E[j,i] ~= rs_j * Q[j,i], rs_j = exp(maxT_j)/127.
// State quantized per-step to u8 against its max: w = round(z * 127/max z).
// Per-step log-growth accumulated exactly for the quantized "shadow chain":
//   r_t = log(sum_j z_j) - log(sum_i w_{t-1,i})   (telescopes exactly)
// Quantization perturbations are mean-zero and contraction-damped.
//
// Parallelism: NCHUNK independent chunks (Perron-Frobenius mixing; BURN
// burn-in steps from uniform start). G chunks share one CTA so each E-row
// load (the L2-bound resource) feeds G dp4a chains at G different timesteps.

#define LNUM     512
#define G        6
#define NCHUNK   888       // = 148 CTAs * G
#define BURN     24
#define NTHREADS 512
#define GOLD_BLOCKS 64

// Device scratch (static; no allocation allowed).
__device__ __align__(16) uint4 g_Q4[(LNUM * LNUM) / 16];  // 256 KB u8 E, packed
__device__ float g_rs[LNUM];        // exp(rowmaxT)/127
__device__ float g_rowmaxT[LNUM];
__device__ float g_acc[NCHUNK];
__device__ float g_gold_part[GOLD_BLOCKS];

// ---------------------------------------------------------------------------
__device__ __forceinline__ float warpSum(float x) {
#pragma unroll
    for (int o = 16; o; o >>= 1) x += __shfl_xor_sync(0xffffffffu, x, o);
    return x;
}
__device__ __forceinline__ float warpMax(float x) {
#pragma unroll
    for (int o = 16; o; o >>= 1) x = fmaxf(x, __shfl_xor_sync(0xffffffffu, x, o));
    return x;
}

// ---------------------------------------------------------------------------
// Prep 1: per-row max of T -> row scale.
// ---------------------------------------------------------------------------
__global__ void prep_rowmax(const float* __restrict__ T) {
    __shared__ float red[4];
    const int jrow = blockIdx.x;
    const int tid  = threadIdx.x;          // 128 threads
    float m = -1e30f;
    for (int i = tid; i < LNUM; i += 128) m = fmaxf(m, T[jrow * LNUM + i]);
    m = warpMax(m);
    if ((tid & 31) == 0) red[tid >> 5] = m;
    __syncthreads();
    if (tid == 0) {
        float mm = fmaxf(fmaxf(red[0], red[1]), fmaxf(red[2], red[3]));
        g_rowmaxT[jrow] = mm;
        g_rs[jrow] = expf(mm) / 127.f;
    }
}

// ---------------------------------------------------------------------------
// Prep 2: Q[j,i] = round(exp(T[j,i]-maxT_j)*127), packed so thread j's
// LDG.128 grabs 16 consecutive i: byte index = (i>>4)*(LNUM*16) + j*16 + (i&15).
// ---------------------------------------------------------------------------
__global__ void prep_quant(const float* __restrict__ T) {
    int idx = blockIdx.x * blockDim.x + threadIdx.x;   // j*LNUM + i
    if (idx >= LNUM * LNUM) return;
    int j = idx >> 9;
    int i = idx & (LNUM - 1);
    float q = expf(T[idx] - g_rowmaxT[j]) * 127.f;
    int wi = __float2int_rn(q);
    wi = min(wi, 127);
    unsigned char* qb = reinterpret_cast<unsigned char*>(g_Q4);
    qb[(i >> 4) * (LNUM * 16) + (j << 4) + (i & 15)] = (unsigned char)wi;
}

// ---------------------------------------------------------------------------
// Main: one CTA advances G independent chunk chains; E row loaded once per
// step, 4 MACs/dp4a. 512 threads: thread j owns output element j.
// ---------------------------------------------------------------------------
__global__ void __launch_bounds__(NTHREADS, 1)
chunk_kernel(const float* __restrict__ logit, int S, int K) {
    __shared__ __align__(16) unsigned char vq[G][LNUM];  // G state vectors, u8
    __shared__ float redm[16][G], redz[16][G], redw[16][G];
    __shared__ float bc[G];

    const int j    = threadIdx.x;
    const int wid  = j >> 5;
    const int lane = j & 31;
    const int cbase = blockIdx.x * G;

    // Per-g schedule (static-indexed -> registers)
    int t0_[G], tend_[G], own_[G];
#pragma unroll
    for (int g = 0; g < G; ++g) {
        int c = cbase + g;
        own_[g]  = 1 + c * K;
        tend_[g] = min(own_[g] + K, S);
        t0_[g]   = (c == 0) ? 1 : own_[g] - BURN;
    }

    const float rs_j = g_rs[j];
    float w_reg[G];
    float accr = 0.f;       // live in (warp g, lane 0) for vector g

    // Init: uniform direction everywhere...
#pragma unroll
    for (int g = 0; g < G; ++g) { vq[g][j] = 127; w_reg[g] = 127.f; }
    __syncthreads();

    // ...except chunk 0 starts exactly from exp(feat_0).
    if (blockIdx.x == 0) {
        float f = logit[j];
        float m = warpMax(f);
        if (lane == 0) redm[wid][0] = m;
        __syncthreads();
        if (wid == 0) {
            float mm = (lane < 16) ? redm[lane][0] : -1e30f;
            mm = warpMax(mm);
            if (lane == 0) bc[0] = mm;
        }
        __syncthreads();
        m = bc[0];
        float e = expf(f - m);
        int wi = __float2int_rn(e * 127.f);
        wi = min(wi, 127);
        vq[0][j] = (unsigned char)wi;
        w_reg[0] = (float)wi;
        float sw = warpSum(w_reg[0]);
        if (lane == 0) redw[wid][0] = sw;
        __syncthreads();
        if (wid == 0) {
            float s = (lane < 16) ? redw[lane][0] : 0.f;
            s = warpSum(s);
            // log sum of shadow u_0 = e^m/127 * w_0
            if (lane == 0) accr = m - logf(127.f) + logf(s);
        }
        __syncthreads();
    }

    const uint4* __restrict__ qrow = g_Q4 + j;
    const int steps = BURN + K;
    float zl[G];

    for (int s = 0; s < steps; ++s) {
        // ---- matvec: y_g[j] = sum_i Q[j,i] * w_g[i]  (exact int32) ----
        unsigned av[G];
#pragma unroll
        for (int g = 0; g < G; ++g) av[g] = 0u;
#pragma unroll 8
        for (int blk = 0; blk < LNUM / 16; ++blk) {
            uint4 q = qrow[blk * LNUM];
#pragma unroll
            for (int g = 0; g < G; ++g) {
                uint4 w = *reinterpret_cast<const uint4*>(&vq[g][blk * 16]);
                av[g] = __dp4a(q.x, w.x, av[g]);
                av[g] = __dp4a(q.y, w.y, av[g]);
                av[g] = __dp4a(q.z, w.z, av[g]);
                av[g] = __dp4a(q.w, w.w, av[g]);
            }
        }

        // ---- phase A: z + warp-level reductions (branches uniform per CTA) --
#pragma unroll
        for (int g = 0; g < G; ++g) {
            int t = t0_[g] + s;
            if (t < tend_[g]) {
                float f  = logit[(t << 9) + j];
                float zg = __expf(f) * (rs_j * (float)av[g]);
                zl[g] = zg;
                float mz = warpMax(zg);
                float sz = warpSum(zg);
                float sw = warpSum(w_reg[g]);    // sum of incoming state (exact)
                if (lane == 0) { redm[wid][g] = mz; redz[wid][g] = sz; redw[wid][g] = sw; }
            }
        }
        __syncthreads();

        // ---- phase B: warp g finalizes vector g ----
        if (wid < G) {
            int c_w   = cbase + wid;
            int own_w = 1 + c_w * K;
            int t0w   = (c_w == 0) ? 1 : own_w - BURN;
            int tw    = t0w + s;
            int tendw = min(own_w + K, S);
            if (tw < tendw) {
                float mz = (lane < 16) ? redm[lane][wid] : -1e30f; mz = warpMax(mz);
                float sz = (lane < 16) ? redz[lane][wid] : 0.f;    sz = warpSum(sz);
                float sw = (lane < 16) ? redw[lane][wid] : 0.f;    sw = warpSum(sw);
                if (lane == 0) {
                    bc[wid] = 127.f / mz;
                    if (tw >= own_w) accr += logf(sz) - logf(sw);
                }
            }
        }
        __syncthreads();

        // ---- phase C: requantize state ----
#pragma unroll
        for (int g = 0; g < G; ++g) {
            int t = t0_[g] + s;
            if (t < tend_[g]) {
                int wi = __float2int_rn(zl[g] * bc[g]);
                wi = min(wi, 127);
                w_reg[g] = (float)wi;
                vq[g][j] = (unsigned char)wi;
            }
        }
        __syncthreads();
    }

    if (wid < G && lane == 0) g_acc[cbase + wid] = accr;
}

// ---------------------------------------------------------------------------
// Gold path score (parallel partials, deterministic).
// ---------------------------------------------------------------------------
__global__ void gold_kernel(const float* __restrict__ logit,
                            const int*   __restrict__ labels,
                            const float* __restrict__ T, int S) {
    __shared__ float red[8];
    const int tid = threadIdx.x;                 // 256
    float p = 0.f;
    for (int t = blockIdx.x * 256 + tid; t < S; t += GOLD_BLOCKS * 256) {
        int lt = labels[t];
        p += logit[(t << 9) + lt];
        if (t >= 1) p += T[(lt << 9) + labels[t - 1]];
    }
    p = warpSum(p);
    if ((tid & 31) == 0) red[tid >> 5] = p;
    __syncthreads();
    if (tid < 32) {
        float s = (tid < 8) ? red[tid] : 0.f;
        s = warpSum(s);
        if (tid == 0) g_gold_part[blockIdx.x] = s;
    }
}

// ---------------------------------------------------------------------------
// Final: parallel strided loads, fixed-order double tree (deterministic).
// ---------------------------------------------------------------------------
__global__ void final_kernel(float* __restrict__ out) {
    const int lane = threadIdx.x;   // 32
    double v = 0.0;
    for (int c = lane; c < NCHUNK; c += 32) v += (double)g_acc[c];
    for (int b = lane; b < GOLD_BLOCKS; b += 32) v -= (double)g_gold_part[b];
#pragma unroll
    for (int o = 16; o; o >>= 1) v += __shfl_xor_sync(0xffffffffu, v, o);
    if (lane == 0) out[0] = (float)v;
}

// ---------------------------------------------------------------------------
extern "C" void kernel_launch(void* const* d_in, const int* in_sizes, int n_in,
                              void* d_out, int out_size) {
    const float* logit  = (const float*)d_in[0];
    const int*   labels = (const int*)d_in[1];
    const float* T      = (const float*)d_in[2];
    const int S = in_sizes[1];                        // 32768
    const int K = (S - 1 + NCHUNK - 1) / NCHUNK;      // 37

    prep_rowmax<<<LNUM, 128>>>(T);
    prep_quant<<<(LNUM * LNUM + 255) / 256, 256>>>(T);
    gold_kernel<<<GOLD_BLOCKS, 256>>>(logit, labels, T, S);
    chunk_kernel<<<NCHUNK / G, NTHREADS>>>(logit, S, K);
    final_kernel<<<1, 32>>>((float*)d_out);
}

// round 7
// speedup vs baseline: 6.2936x; 1.1036x over previous
#include <cuda_runtime.h>

// CRF forward (log-partition) minus gold-path score — tensor-core (IMMA) edition.
//
// Exp-domain chunked chains (see R5/R6): u_t = diag(exp(feat_t)) * E * u_{t-1},
// E = exp(T) quantized per-row to s8 (0..127), state requantized to s8 per step,
// per-step log-growth telescoped exactly for the quantized shadow chain.
//
// Matvec = 512x512xN s8 GEMM per step via mma.sync.m16n8k32.s32.s8.s8.s32.
// E is pre-packed into A-fragment order so each (mtile,kchunk) A fragment is a
// single coalesced LDG.128 per thread (streamed from L2; E = 256 KB resident).
// N = 16 chains per CTA share every E byte read. State lives in smem (B frags).

#define LNUM  512
#define NCTA  148
#define NCH   16                  // chains per CTA (two n8 MMA groups)
#define NCHUNK (NCTA * NCH)       // 2368
#define BURN  24
#define GOLD_BLOCKS 64
#define VPITCH 528                // vq row pitch (bank-conflict-free B frags)

// Device scratch (static; no allocation allowed).
__device__ __align__(16) unsigned char g_A[LNUM * LNUM];  // E s8, A-fragment order
__device__ float g_rs[LNUM];
__device__ float g_rowmax[LNUM];
__device__ float g_acc[NCHUNK];
__device__ float g_gold_part[GOLD_BLOCKS];

// ---------------------------------------------------------------------------
__device__ __forceinline__ float warpSum(float x) {
#pragma unroll
    for (int o = 16; o; o >>= 1) x += __shfl_xor_sync(0xffffffffu, x, o);
    return x;
}
__device__ __forceinline__ float warpMax(float x) {
#pragma unroll
    for (int o = 16; o; o >>= 1) x = fmaxf(x, __shfl_xor_sync(0xffffffffu, x, o));
    return x;
}

__device__ __forceinline__ void imma(int& d0, int& d1, int& d2, int& d3,
                                     unsigned a0, unsigned a1, unsigned a2, unsigned a3,
                                     unsigned b0, unsigned b1) {
    asm volatile(
        "mma.sync.aligned.m16n8k32.row.col.s32.s8.s8.s32 "
        "{%0,%1,%2,%3},{%4,%5,%6,%7},{%8,%9},{%0,%1,%2,%3};"
        : "+r"(d0), "+r"(d1), "+r"(d2), "+r"(d3)
        : "r"(a0), "r"(a1), "r"(a2), "r"(a3), "r"(b0), "r"(b1));
}

// ---------------------------------------------------------------------------
// Prep 1: per-row max of T -> row scale rs_j = exp(maxT_j)/127.
// ---------------------------------------------------------------------------
__global__ void prep_rowmax(const float* __restrict__ T) {
    __shared__ float red[4];
    const int jrow = blockIdx.x;
    const int tid  = threadIdx.x;          // 128
    float m = -1e30f;
    for (int i = tid; i < LNUM; i += 128) m = fmaxf(m, T[jrow * LNUM + i]);
    m = warpMax(m);
    if ((tid & 31) == 0) red[tid >> 5] = m;
    __syncthreads();
    if (tid == 0) {
        float mm = fmaxf(fmaxf(red[0], red[1]), fmaxf(red[2], red[3]));
        g_rowmax[jrow] = mm;
        g_rs[jrow] = expf(mm) / 127.f;
    }
}

// ---------------------------------------------------------------------------
// Prep 2: Q[j,k] = round(exp(T[j,k]-maxT_j)*127), scattered into the exact
// mma.m16n8k32 A-fragment layout:
//   mtile m = j>>4, row-in-tile r = j&15, gid = r&7, rhalf = r>>3
//   kchunk kc = k>>5, kk = k&31, tig = (kk>>2)&3, khalf = kk>>4, b = kk&3
//   lane = gid*4+tig, reg = rhalf + 2*khalf   (a0..a3)
//   byte = (((m*16+kc)*32 + lane)*4 + reg)*4 + b
// ---------------------------------------------------------------------------
__global__ void prep_quant(const float* __restrict__ T) {
    int idx = blockIdx.x * blockDim.x + threadIdx.x;   // j*512 + k
    if (idx >= LNUM * LNUM) return;
    int j = idx >> 9;
    int k = idx & (LNUM - 1);
    float q = expf(T[idx] - g_rowmax[j]) * 127.f;
    int wi = min(__float2int_rn(q), 127);

    int m = j >> 4, r = j & 15, gid = r & 7, rh = r >> 3;
    int kc = k >> 5, kk = k & 31, tig = (kk >> 2) & 3, kh = kk >> 4, b = kk & 3;
    int lane = gid * 4 + tig;
    int reg  = rh + 2 * kh;
    g_A[(((m * 16 + kc) * 32 + lane) * 4 + reg) * 4 + b] = (unsigned char)wi;
}

// ---------------------------------------------------------------------------
// Main: one CTA = 16 chains, 512 threads = 16 warps; warp w owns mtiles
// {2w, 2w+1} in the GEMM and chain w in the reductions/requant.
// ---------------------------------------------------------------------------
__global__ void __launch_bounds__(512, 1)
chunk_kernel(const float* __restrict__ logit, int S, int K) {
    __shared__ __align__(16) unsigned char vq[NCH * VPITCH];  // state, s8
    __shared__ __align__(16) float zbuf[NCH * LNUM];          // 32 KB
    __shared__ float s_rs[LNUM];
    __shared__ float s_bc[NCH];
    __shared__ float s_sw[NCH];
    __shared__ float s_red[16];
    __shared__ float s_m;

    const int tid  = threadIdx.x;
    const int wid  = tid >> 5;
    const int lane = tid & 31;
    const int gid  = lane >> 2;
    const int tig  = lane & 3;

    s_rs[tid] = g_rs[tid];

    // --- warp-as-chain schedule (chain c = blockIdx.x*16 + wid) ---
    const int cg_w   = blockIdx.x * NCH + wid;
    const int own_w  = 1 + cg_w * K;
    const int tend_w = min(own_w + K, S);
    const int t0_w   = (cg_w == 0) ? 1 : max(1, own_w - BURN);

    // --- epilogue chains for this thread: c_l = 8h + tig*2 + q ---
    int t0_e[2][2], tend_e[2][2];
#pragma unroll
    for (int h = 0; h < 2; ++h)
#pragma unroll
        for (int q = 0; q < 2; ++q) {
            int cl = 8 * h + tig * 2 + q;
            int cg = blockIdx.x * NCH + cl;
            int ow = 1 + cg * K;
            tend_e[h][q] = min(ow + K, S);
            t0_e[h][q]   = (cg == 0) ? 1 : max(1, ow - BURN);
        }

    // --- init: uniform state everywhere ---
#pragma unroll
    for (int c = 0; c < NCH; ++c) vq[c * VPITCH + tid] = 127;
    if (tid < NCH) s_sw[tid] = 127.f * (float)LNUM;
    __syncthreads();

    float accr = 0.f;   // live in lane 0 of warp wid (chain wid)

    // --- chain 0 exact start from exp(feat_0) (block 0 only) ---
    if (blockIdx.x == 0) {
        float f = logit[tid];
        float m = warpMax(f);
        if (lane == 0) s_red[wid] = m;
        __syncthreads();
        if (wid == 0) {
            float mm = (lane < 16) ? s_red[lane] : -1e30f;
            mm = warpMax(mm);
            if (lane == 0) s_m = mm;
        }
        __syncthreads();
        float m_all = s_m;
        float e = expf(f - m_all);
        int wi = min(__float2int_rn(e * 127.f), 127);
        vq[0 * VPITCH + tid] = (unsigned char)wi;
        float sw = warpSum((float)wi);
        if (lane == 0) s_red[wid] = sw;
        __syncthreads();
        if (wid == 0) {
            float s = (lane < 16) ? s_red[lane] : 0.f;
            s = warpSum(s);
            if (lane == 0) { s_sw[0] = s; accr = m_all - logf(127.f) + logf(s); }
        }
        __syncthreads();
    }

    const uint4* __restrict__ A4 = reinterpret_cast<const uint4*>(g_A);
    const int m0 = wid * 2, m1 = wid * 2 + 1;
    const int jl0 = m0 * 16 + gid, jl1 = jl0 + 8;
    const int jl2 = m1 * 16 + gid, jl3 = jl2 + 8;
    const int steps = BURN + K;

    for (int s = 0; s < steps; ++s) {
        // ---- prefetch logit for this step (before the GEMM) ----
        float fv[2][2][4];
        bool  act[2][2];
#pragma unroll
        for (int h = 0; h < 2; ++h)
#pragma unroll
            for (int q = 0; q < 2; ++q) {
                int t = t0_e[h][q] + s;
                bool a = (t < tend_e[h][q]);
                act[h][q] = a;
                if (a) {
                    const float* lt = logit + ((long)t << 9);
                    fv[h][q][0] = lt[jl0];
                    fv[h][q][1] = lt[jl1];
                    fv[h][q][2] = lt[jl2];
                    fv[h][q][3] = lt[jl3];
                }
            }

        // ---- GEMM: D[512, 16] = E(s8) @ state(s8), this warp does 2 mtiles --
        int d[2][2][4];
#pragma unroll
        for (int mi = 0; mi < 2; ++mi)
#pragma unroll
            for (int h = 0; h < 2; ++h)
#pragma unroll
                for (int r = 0; r < 4; ++r) d[mi][h][r] = 0;

#pragma unroll
        for (int kc = 0; kc < 16; ++kc) {
            const int kb = kc * 32 + tig * 4;
            unsigned b00 = *reinterpret_cast<const unsigned*>(&vq[gid * VPITCH + kb]);
            unsigned b01 = *reinterpret_cast<const unsigned*>(&vq[gid * VPITCH + kb + 16]);
            unsigned b10 = *reinterpret_cast<const unsigned*>(&vq[(gid + 8) * VPITCH + kb]);
            unsigned b11 = *reinterpret_cast<const unsigned*>(&vq[(gid + 8) * VPITCH + kb + 16]);
            uint4 A0 = A4[(m0 * 16 + kc) * 32 + lane];
            uint4 A1 = A4[(m1 * 16 + kc) * 32 + lane];
            imma(d[0][0][0], d[0][0][1], d[0][0][2], d[0][0][3], A0.x, A0.y, A0.z, A0.w, b00, b01);
            imma(d[0][1][0], d[0][1][1], d[0][1][2], d[0][1][3], A0.x, A0.y, A0.z, A0.w, b10, b11);
            imma(d[1][0][0], d[1][0][1], d[1][0][2], d[1][0][3], A1.x, A1.y, A1.z, A1.w, b00, b01);
            imma(d[1][1][0], d[1][1][1], d[1][1][2], d[1][1][3], A1.x, A1.y, A1.z, A1.w, b10, b11);
        }

        // ---- epilogue: z = exp(f) * rs_j * y, scatter to zbuf ----
        // D mapping: d[mi][h][0]=(j_lo, cA) d[1]=(j_lo, cB) d[2]=(j_hi, cA) d[3]=(j_hi, cB)
        // with cA = 8h + tig*2, cB = cA+1.
#pragma unroll
        for (int mi = 0; mi < 2; ++mi) {
            int jlo = (mi == 0) ? jl0 : jl2;
            int jhi = (mi == 0) ? jl1 : jl3;
            float rlo = s_rs[jlo], rhi = s_rs[jhi];
#pragma unroll
            for (int h = 0; h < 2; ++h) {
                int cA = 8 * h + tig * 2;
                if (act[h][0]) {
                    zbuf[cA * LNUM + jlo] = __expf(fv[h][0][mi * 2 + 0]) * rlo * (float)d[mi][h][0];
                    zbuf[cA * LNUM + jhi] = __expf(fv[h][0][mi * 2 + 1]) * rhi * (float)d[mi][h][2];
                }
                if (act[h][1]) {
                    zbuf[(cA + 1) * LNUM + jlo] = __expf(fv[h][1][mi * 2 + 0]) * rlo * (float)d[mi][h][1];
                    zbuf[(cA + 1) * LNUM + jhi] = __expf(fv[h][1][mi * 2 + 1]) * rhi * (float)d[mi][h][3];
                }
            }
        }
        __syncthreads();

        // ---- per-chain reduction: warp wid handles chain wid ----
        {
            int t = t0_w + s;
            if (t < tend_w) {
                float mx = -1e30f, sm = 0.f;
#pragma unroll
                for (int k = 0; k < 16; ++k) {
                    float z = zbuf[wid * LNUM + lane + 32 * k];
                    mx = fmaxf(mx, z);
                    sm += z;
                }
                mx = warpMax(mx);
                sm = warpSum(sm);
                if (lane == 0) {
                    s_bc[wid] = 127.f / mx;
                    if (t >= own_w) accr += logf(sm) - logf(s_sw[wid]);
                }
            }
        }
        __syncthreads();

        // ---- requant: warp wid requantizes chain wid's state ----
        {
            int t = t0_w + s;
            if (t < tend_w) {
                float bcv = s_bc[wid];
                const float4* zb = reinterpret_cast<const float4*>(&zbuf[wid * LNUM + lane * 16]);
                unsigned pk[4];
                int lsum = 0;
#pragma unroll
                for (int p = 0; p < 4; ++p) {
                    float4 z = zb[p];
                    int w0 = min(__float2int_rn(z.x * bcv), 127);
                    int w1 = min(__float2int_rn(z.y * bcv), 127);
                    int w2 = min(__float2int_rn(z.z * bcv), 127);
                    int w3 = min(__float2int_rn(z.w * bcv), 127);
                    lsum += w0 + w1 + w2 + w3;
                    pk[p] = (unsigned)w0 | ((unsigned)w1 << 8) | ((unsigned)w2 << 16) | ((unsigned)w3 << 24);
                }
                *reinterpret_cast<uint4*>(&vq[wid * VPITCH + lane * 16]) =
                    make_uint4(pk[0], pk[1], pk[2], pk[3]);
                unsigned tot = __reduce_add_sync(0xffffffffu, (unsigned)lsum);
                if (lane == 0) s_sw[wid] = (float)tot;
            }
        }
        __syncthreads();
    }

    if (lane == 0) g_acc[cg_w] = accr;
}

// ---------------------------------------------------------------------------
// Gold path score (parallel partials, deterministic).
// ---------------------------------------------------------------------------
__global__ void gold_kernel(const float* __restrict__ logit,
                            const int*   __restrict__ labels,
                            const float* __restrict__ T, int S) {
    __shared__ float red[8];
    const int tid = threadIdx.x;                 // 256
    float p = 0.f;
    for (int t = blockIdx.x * 256 + tid; t < S; t += GOLD_BLOCKS * 256) {
        int lt = labels[t];
        p += logit[(t << 9) + lt];
        if (t >= 1) p += T[(lt << 9) + labels[t - 1]];
    }
    p = warpSum(p);
    if ((tid & 31) == 0) red[tid >> 5] = p;
    __syncthreads();
    if (tid < 32) {
        float s = (tid < 8) ? red[tid] : 0.f;
        s = warpSum(s);
        if (tid == 0) g_gold_part[blockIdx.x] = s;
    }
}

// ---------------------------------------------------------------------------
// Final: 256-thread deterministic fixed-order double tree.
// ---------------------------------------------------------------------------
__global__ void final_kernel(float* __restrict__ out) {
    __shared__ double sd[256];
    const int tid = threadIdx.x;
    double v = 0.0;
    for (int c = tid; c < NCHUNK; c += 256) v += (double)g_acc[c];
    for (int b = tid; b < GOLD_BLOCKS; b += 256) v -= (double)g_gold_part[b];
    sd[tid] = v;
    __syncthreads();
    for (int o = 128; o; o >>= 1) {
        if (tid < o) sd[tid] += sd[tid + o];
        __syncthreads();
    }
    if (tid == 0) out[0] = (float)sd[0];
}

// ---------------------------------------------------------------------------
extern "C" void kernel_launch(void* const* d_in, const int* in_sizes, int n_in,
                              void* d_out, int out_size) {
    const float* logit  = (const float*)d_in[0];
    const int*   labels = (const int*)d_in[1];
    const float* T      = (const float*)d_in[2];
    const int S = in_sizes[1];                        // 32768
    const int K = (S - 1 + NCHUNK - 1) / NCHUNK;      // 14

    prep_rowmax<<<LNUM, 128>>>(T);
    prep_quant<<<(LNUM * LNUM + 255) / 256, 256>>>(T);
    gold_kernel<<<GOLD_BLOCKS, 256>>>(logit, labels, T, S);
    chunk_kernel<<<NCTA, 512>>>(logit, S, K);
    final_kernel<<<1, 256>>>((float*)d_out);
}

// round 8
// speedup vs baseline: 11.1660x; 1.7742x over previous
#include <cuda_runtime.h>

// CRF forward (log-partition) minus gold-path score — IMMA edition, v2.
//
// Exp-domain chunked chains: u_t = diag(exp(feat_t)) * E * u_{t-1}.
// E = exp(T) quantized per-row to s8 (0..127); state requantized to s8 each
// step; per-step log-growth telescoped exactly for the quantized shadow chain.
//
// v2 vs v1: NCH 16->8 and BURN 24->12 cut total chain-steps 90K->47K (the
// tensor pipe was the binding resource at 78%); one warp owns one chain so
// the max/requant phase is warp-local (2 barriers/step instead of 3).

#define LNUM  512
#define NCTA  148
#define NCH   8                   // chains per CTA (one n8 MMA group)
#define NCHUNK (NCTA * NCH)       // 1184
#define BURN  12
#define GOLD_BLOCKS 64
#define VPITCH 528                // vq row pitch (B-fragment reads conflict-free)
#define ZP     516                // zbuf row pitch (epilogue scatter conflict-free)

// Device scratch (static; no allocation allowed).
__device__ __align__(16) unsigned char g_A[LNUM * LNUM];  // E s8, A-fragment order
__device__ float g_rs[LNUM];
__device__ float g_rowmax[LNUM];
__device__ float g_acc[NCHUNK];
__device__ float g_gold_part[GOLD_BLOCKS];

// ---------------------------------------------------------------------------
__device__ __forceinline__ float warpSum(float x) {
#pragma unroll
    for (int o = 16; o; o >>= 1) x += __shfl_xor_sync(0xffffffffu, x, o);
    return x;
}
__device__ __forceinline__ float warpMax(float x) {
#pragma unroll
    for (int o = 16; o; o >>= 1) x = fmaxf(x, __shfl_xor_sync(0xffffffffu, x, o));
    return x;
}

__device__ __forceinline__ void imma(int& d0, int& d1, int& d2, int& d3,
                                     unsigned a0, unsigned a1, unsigned a2, unsigned a3,
                                     unsigned b0, unsigned b1) {
    asm volatile(
        "mma.sync.aligned.m16n8k32.row.col.s32.s8.s8.s32 "
        "{%0,%1,%2,%3},{%4,%5,%6,%7},{%8,%9},{%0,%1,%2,%3};"
        : "+r"(d0), "+r"(d1), "+r"(d2), "+r"(d3)
        : "r"(a0), "r"(a1), "r"(a2), "r"(a3), "r"(b0), "r"(b1));
}

// ---------------------------------------------------------------------------
// Prep 1: per-row max of T -> row scale rs_j = exp(maxT_j)/127.
// ---------------------------------------------------------------------------
__global__ void prep_rowmax(const float* __restrict__ T) {
    __shared__ float red[4];
    const int jrow = blockIdx.x;
    const int tid  = threadIdx.x;          // 128
    float m = -1e30f;
    for (int i = tid; i < LNUM; i += 128) m = fmaxf(m, T[jrow * LNUM + i]);
    m = warpMax(m);
    if ((tid & 31) == 0) red[tid >> 5] = m;
    __syncthreads();
    if (tid == 0) {
        float mm = fmaxf(fmaxf(red[0], red[1]), fmaxf(red[2], red[3]));
        g_rowmax[jrow] = mm;
        g_rs[jrow] = expf(mm) / 127.f;
    }
}

// ---------------------------------------------------------------------------
// Prep 2: Q[j,k] = round(exp(T[j,k]-maxT_j)*127), scattered into the exact
// mma.m16n8k32 A-fragment layout (verified in R6):
//   byte = (((m*16+kc)*32 + gid*4+tig)*4 + (rhalf+2*khalf))*4 + (kk&3)
// ---------------------------------------------------------------------------
__global__ void prep_quant(const float* __restrict__ T) {
    int idx = blockIdx.x * blockDim.x + threadIdx.x;   // j*512 + k
    if (idx >= LNUM * LNUM) return;
    int j = idx >> 9;
    int k = idx & (LNUM - 1);
    float q = expf(T[idx] - g_rowmax[j]) * 127.f;
    int wi = min(__float2int_rn(q), 127);

    int m = j >> 4, r = j & 15, gid = r & 7, rh = r >> 3;
    int kc = k >> 5, kk = k & 31, tig = (kk >> 2) & 3, kh = kk >> 4, b = kk & 3;
    g_A[(((m * 16 + kc) * 32 + gid * 4 + tig) * 4 + (rh + 2 * kh)) * 4 + b] =
        (unsigned char)wi;
}

// ---------------------------------------------------------------------------
// Main: one CTA = 8 chains, 512 threads = 16 warps. In the GEMM, warp w owns
// mtiles {2w, 2w+1} (all 32). In the reduction/requant, warp w (w<8) owns
// chain w — max/sum/requant all warp-local, no smem handoff.
// ---------------------------------------------------------------------------
__global__ void __launch_bounds__(512, 1)
chunk_kernel(const float* __restrict__ logit, int S, int K) {
    __shared__ __align__(16) unsigned char vq[NCH * VPITCH];  // state, s8
    __shared__ __align__(16) float zbuf[NCH * ZP];
    __shared__ float s_rs[LNUM];
    __shared__ float s_red[16];
    __shared__ float s_m, s_s0;

    const int tid  = threadIdx.x;
    const int wid  = tid >> 5;
    const int lane = tid & 31;
    const int gid  = lane >> 2;
    const int tig  = lane & 3;

    s_rs[tid] = g_rs[tid];

    // --- warp-as-chain schedule (chain wid for wid<8) ---
    const int cg_w   = blockIdx.x * NCH + wid;
    const int own_w  = 1 + cg_w * K;
    const int tend_w = min(own_w + K, S);
    const int t0_w   = (cg_w == 0) ? 1 : own_w - BURN;

    // --- epilogue chains for this thread: c = 2*tig + q ---
    int t0_e[2], tend_e[2];
#pragma unroll
    for (int q = 0; q < 2; ++q) {
        int cg = blockIdx.x * NCH + 2 * tig + q;
        int ow = 1 + cg * K;
        tend_e[q] = min(ow + K, S);
        t0_e[q]   = (cg == 0) ? 1 : ow - BURN;
    }

    // --- init: uniform state everywhere ---
#pragma unroll
    for (int c = 0; c < NCH; ++c) vq[c * VPITCH + tid] = 127;
    __syncthreads();

    float sw_reg = 127.f * (float)LNUM;   // sum of incoming state (exact int)
    float accr   = 0.f;                   // live in lane 0 of warp wid (wid<8)

    // --- chain 0 exact start from exp(feat_0) (block 0 only) ---
    if (blockIdx.x == 0) {
        float f = logit[tid];
        float m = warpMax(f);
        if (lane == 0) s_red[wid] = m;
        __syncthreads();
        if (wid == 0) {
            float mm = (lane < 16) ? s_red[lane] : -1e30f;
            mm = warpMax(mm);
            if (lane == 0) s_m = mm;
        }
        __syncthreads();
        float m_all = s_m;
        int wi = min(__float2int_rn(expf(f - m_all) * 127.f), 127);
        vq[tid] = (unsigned char)wi;
        float sw = warpSum((float)wi);
        if (lane == 0) s_red[wid] = sw;
        __syncthreads();
        if (wid == 0) {
            float s = (lane < 16) ? s_red[lane] : 0.f;
            s = warpSum(s);
            if (lane == 0) s_s0 = s;
        }
        __syncthreads();
        if (wid == 0) {
            sw_reg = s_s0;
            if (lane == 0) accr = m_all - logf(127.f) + logf(s_s0);
        }
        __syncthreads();
    }

    const uint4* __restrict__ A4 = reinterpret_cast<const uint4*>(g_A);
    const int m0 = wid * 2, m1 = wid * 2 + 1;
    const int jl0 = m0 * 16 + gid, jl1 = jl0 + 8;
    const int jl2 = m1 * 16 + gid, jl3 = jl2 + 8;
    const float rl0 = s_rs[jl0], rl1 = s_rs[jl1], rl2 = s_rs[jl2], rl3 = s_rs[jl3];
    const int steps = BURN + K;

    for (int s = 0; s < steps; ++s) {
        // ---- prefetch logit for this step ----
        float fv[2][4];
        bool  act[2];
#pragma unroll
        for (int q = 0; q < 2; ++q) {
            int t = t0_e[q] + s;
            act[q] = (t < tend_e[q]);
            if (act[q]) {
                const float* lt = logit + ((long)t << 9);
                fv[q][0] = lt[jl0];
                fv[q][1] = lt[jl1];
                fv[q][2] = lt[jl2];
                fv[q][3] = lt[jl3];
            }
        }

        // ---- GEMM: D[512, 8] = E(s8) @ state(s8); this warp: 2 mtiles ----
        int d0[4] = {0, 0, 0, 0}, d1[4] = {0, 0, 0, 0};
#pragma unroll
        for (int kc = 0; kc < 16; ++kc) {
            const int kb = kc * 32 + tig * 4;
            unsigned b0 = *reinterpret_cast<const unsigned*>(&vq[gid * VPITCH + kb]);
            unsigned b1 = *reinterpret_cast<const unsigned*>(&vq[gid * VPITCH + kb + 16]);
            uint4 A0 = A4[(m0 * 16 + kc) * 32 + lane];
            uint4 A1 = A4[(m1 * 16 + kc) * 32 + lane];
            imma(d0[0], d0[1], d0[2], d0[3], A0.x, A0.y, A0.z, A0.w, b0, b1);
            imma(d1[0], d1[1], d1[2], d1[3], A1.x, A1.y, A1.z, A1.w, b0, b1);
        }

        // ---- epilogue: z = exp(f) * rs_j * y  (cols: 2tig+q) ----
#pragma unroll
        for (int q = 0; q < 2; ++q) {
            if (act[q]) {
                float* zr = zbuf + (2 * tig + q) * ZP;
                zr[jl0] = __expf(fv[q][0]) * rl0 * (float)d0[q];
                zr[jl1] = __expf(fv[q][1]) * rl1 * (float)d0[q + 2];
                zr[jl2] = __expf(fv[q][2]) * rl2 * (float)d1[q];
                zr[jl3] = __expf(fv[q][3]) * rl3 * (float)d1[q + 2];
            }
        }
        __syncthreads();

        // ---- warp wid: reduce + requant chain wid (warp-local, no handoff) --
        if (wid < NCH) {
            int t = t0_w + s;
            if (t < tend_w) {
                float mx = -1e30f, sm = 0.f;
                const float* zr = zbuf + wid * ZP;
#pragma unroll
                for (int k = 0; k < 16; ++k) {
                    float z = zr[lane + 32 * k];
                    mx = fmaxf(mx, z);
                    sm += z;
                }
                mx = warpMax(mx);           // all lanes
                sm = warpSum(sm);           // all lanes
                float bcv = 127.f / mx;

                const float4* zb = reinterpret_cast<const float4*>(zr + lane * 16);
                unsigned pk[4];
                int lsum = 0;
#pragma unroll
                for (int p = 0; p < 4; ++p) {
                    float4 z = zb[p];
                    int w0 = min(__float2int_rn(z.x * bcv), 127);
                    int w1 = min(__float2int_rn(z.y * bcv), 127);
                    int w2 = min(__float2int_rn(z.z * bcv), 127);
                    int w3 = min(__float2int_rn(z.w * bcv), 127);
                    lsum += w0 + w1 + w2 + w3;
                    pk[p] = (unsigned)w0 | ((unsigned)w1 << 8) |
                            ((unsigned)w2 << 16) | ((unsigned)w3 << 24);
                }
                *reinterpret_cast<uint4*>(&vq[wid * VPITCH + lane * 16]) =
                    make_uint4(pk[0], pk[1], pk[2], pk[3]);
                unsigned tot = __reduce_add_sync(0xffffffffu, (unsigned)lsum);
                if (lane == 0 && t >= own_w) accr += logf(sm) - logf(sw_reg);
                sw_reg = (float)tot;
            }
        }
        __syncthreads();
    }

    if (wid < NCH && lane == 0) g_acc[cg_w] = accr;
}

// ---------------------------------------------------------------------------
// Gold path score (parallel partials, deterministic).
// ---------------------------------------------------------------------------
__global__ void gold_kernel(const float* __restrict__ logit,
                            const int*   __restrict__ labels,
                            const float* __restrict__ T, int S) {
    __shared__ float red[8];
    const int tid = threadIdx.x;                 // 256
    float p = 0.f;
    for (int t = blockIdx.x * 256 + tid; t < S; t += GOLD_BLOCKS * 256) {
        int lt = labels[t];
        p += logit[(t << 9) + lt];
        if (t >= 1) p += T[(lt << 9) + labels[t - 1]];
    }
    p = warpSum(p);
    if ((tid & 31) == 0) red[tid >> 5] = p;
    __syncthreads();
    if (tid < 32) {
        float s = (tid < 8) ? red[tid] : 0.f;
        s = warpSum(s);
        if (tid == 0) g_gold_part[blockIdx.x] = s;
    }
}

// ---------------------------------------------------------------------------
// Final: 256-thread deterministic fixed-order double tree.
// ---------------------------------------------------------------------------
__global__ void final_kernel(float* __restrict__ out) {
    __shared__ double sd[256];
    const int tid = threadIdx.x;
    double v = 0.0;
    for (int c = tid; c < NCHUNK; c += 256) v += (double)g_acc[c];
    for (int b = tid; b < GOLD_BLOCKS; b += 256) v -= (double)g_gold_part[b];
    sd[tid] = v;
    __syncthreads();
    for (int o = 128; o; o >>= 1) {
        if (tid < o) sd[tid] += sd[tid + o];
        __syncthreads();
    }
    if (tid == 0) out[0] = (float)sd[0];
}

// ---------------------------------------------------------------------------
extern "C" void kernel_launch(void* const* d_in, const int* in_sizes, int n_in,
                              void* d_out, int out_size) {
    const float* logit  = (const float*)d_in[0];
    const int*   labels = (const int*)d_in[1];
    const float* T      = (const float*)d_in[2];
    const int S = in_sizes[1];                        // 32768
    const int K = (S - 1 + NCHUNK - 1) / NCHUNK;      // 28

    prep_rowmax<<<LNUM, 128>>>(T);
    prep_quant<<<(LNUM * LNUM + 255) / 256, 256>>>(T);
    gold_kernel<<<GOLD_BLOCKS, 256>>>(logit, labels, T, S);
    chunk_kernel<<<NCTA, 512>>>(logit, S, K);
    final_kernel<<<1, 256>>>((float*)d_out);
}

// round 9
// speedup vs baseline: 11.6009x; 1.0390x over previous
#include <cuda_runtime.h>

// CRF forward (log-partition) minus gold-path score — IMMA edition, v3.
//
// Exp-domain chunked chains: u_t = diag(exp(feat_t)) * E * u_{t-1}.
// E = exp(T) quantized per-row to s8 (0..127); state requantized to s8 each
// step; per-step log-growth telescoped exactly for the quantized shadow chain.
//
// v3 vs v2: 2 CTAs per SM (256 threads / 8 warps / 8 chains each) so one
// CTA's epilogue+barriers hide under the other's tensor work; every warp owns
// a chain in the epilogue (no idle half). BURN 12->6 (rel_err was bit-identical
// from 24->12; quantization dominates). Total chain-steps unchanged (47.4K) —
// the gain is tensor-pipe utilization 74% -> ~90%.

#define LNUM  512
#define NCTA  296                 // 2 per SM
#define NCH   8                   // chains per CTA (one n8 MMA group)
#define NCHUNK (NCTA * NCH)       // 2368
#define BURN  6
#define GOLD_BLOCKS 64
#define VPITCH 528                // vq row pitch (B-fragment reads conflict-free)
#define ZP     516                // zbuf row pitch (epilogue scatter conflict-free)

// Device scratch (static; no allocation allowed).
__device__ __align__(16) unsigned char g_A[LNUM * LNUM];  // E s8, A-fragment order
__device__ float g_rs[LNUM];
__device__ float g_rowmax[LNUM];
__device__ float g_acc[NCHUNK];
__device__ float g_gold_part[GOLD_BLOCKS];

// ---------------------------------------------------------------------------
__device__ __forceinline__ float warpSum(float x) {
#pragma unroll
    for (int o = 16; o; o >>= 1) x += __shfl_xor_sync(0xffffffffu, x, o);
    return x;
}
__device__ __forceinline__ float warpMax(float x) {
#pragma unroll
    for (int o = 16; o; o >>= 1) x = fmaxf(x, __shfl_xor_sync(0xffffffffu, x, o));
    return x;
}

__device__ __forceinline__ void imma(int& d0, int& d1, int& d2, int& d3,
                                     unsigned a0, unsigned a1, unsigned a2, unsigned a3,
                                     unsigned b0, unsigned b1) {
    asm volatile(
        "mma.sync.aligned.m16n8k32.row.col.s32.s8.s8.s32 "
        "{%0,%1,%2,%3},{%4,%5,%6,%7},{%8,%9},{%0,%1,%2,%3};"
        : "+r"(d0), "+r"(d1), "+r"(d2), "+r"(d3)
        : "r"(a0), "r"(a1), "r"(a2), "r"(a3), "r"(b0), "r"(b1));
}

// ---------------------------------------------------------------------------
// Prep 1: per-row max of T -> row scale rs_j = exp(maxT_j)/127.
// ---------------------------------------------------------------------------
__global__ void prep_rowmax(const float* __restrict__ T) {
    __shared__ float red[4];
    const int jrow = blockIdx.x;
    const int tid  = threadIdx.x;          // 128
    float m = -1e30f;
    for (int i = tid; i < LNUM; i += 128) m = fmaxf(m, T[jrow * LNUM + i]);
    m = warpMax(m);
    if ((tid & 31) == 0) red[tid >> 5] = m;
    __syncthreads();
    if (tid == 0) {
        float mm = fmaxf(fmaxf(red[0], red[1]), fmaxf(red[2], red[3]));
        g_rowmax[jrow] = mm;
        g_rs[jrow] = expf(mm) / 127.f;
    }
}

// ---------------------------------------------------------------------------
// Prep 2: Q[j,k] = round(exp(T[j,k]-maxT_j)*127), scattered into the exact
// mma.m16n8k32 A-fragment layout (verified in R6/R7):
//   byte = (((m*16+kc)*32 + gid*4+tig)*4 + (rhalf+2*khalf))*4 + (kk&3)
// ---------------------------------------------------------------------------
__global__ void prep_quant(const float* __restrict__ T) {
    int idx = blockIdx.x * blockDim.x + threadIdx.x;   // j*512 + k
    if (idx >= LNUM * LNUM) return;
    int j = idx >> 9;
    int k = idx & (LNUM - 1);
    float q = expf(T[idx] - g_rowmax[j]) * 127.f;
    int wi = min(__float2int_rn(q), 127);

    int m = j >> 4, r = j & 15, gid = r & 7, rh = r >> 3;
    int kc = k >> 5, kk = k & 31, tig = (kk >> 2) & 3, kh = kk >> 4, b = kk & 3;
    g_A[(((m * 16 + kc) * 32 + gid * 4 + tig) * 4 + (rh + 2 * kh)) * 4 + b] =
        (unsigned char)wi;
}

// ---------------------------------------------------------------------------
// Main: one CTA = 8 chains, 256 threads = 8 warps, 2 CTAs per SM.
// GEMM: warp w owns mtiles {4w..4w+3}. Epilogue: warp w owns chain w.
// ---------------------------------------------------------------------------
__global__ void __launch_bounds__(256, 2)
chunk_kernel(const float* __restrict__ logit, int S, int K) {
    __shared__ __align__(16) unsigned char vq[NCH * VPITCH];  // state, s8
    __shared__ __align__(16) float zbuf[NCH * ZP];
    __shared__ float s_rs[LNUM];
    __shared__ float s_red[8];
    __shared__ float s_m, s_s0;

    const int tid  = threadIdx.x;
    const int wid  = tid >> 5;          // 0..7
    const int lane = tid & 31;
    const int gid  = lane >> 2;
    const int tig  = lane & 3;

    s_rs[tid]       = g_rs[tid];
    s_rs[tid + 256] = g_rs[tid + 256];

    // --- warp-as-chain schedule (chain wid) ---
    const int cg_w   = blockIdx.x * NCH + wid;
    const int own_w  = 1 + cg_w * K;
    const int tend_w = min(own_w + K, S);
    const int t0_w   = (cg_w == 0) ? 1 : own_w - BURN;

    // --- epilogue chains for this thread: c = 2*tig + q ---
    int t0_e[2], tend_e[2];
#pragma unroll
    for (int q = 0; q < 2; ++q) {
        int cg = blockIdx.x * NCH + 2 * tig + q;
        int ow = 1 + cg * K;
        tend_e[q] = min(ow + K, S);
        t0_e[q]   = (cg == 0) ? 1 : ow - BURN;
    }

    // --- init: uniform state everywhere ---
#pragma unroll
    for (int c = 0; c < NCH; ++c) {
        vq[c * VPITCH + tid]       = 127;
        vq[c * VPITCH + tid + 256] = 127;
    }
    __syncthreads();

    float sw_reg = 127.f * (float)LNUM;   // sum of incoming state (exact int)
    float accr   = 0.f;                   // live in lane 0 of warp wid

    // --- chain 0 exact start from exp(feat_0) (block 0 only) ---
    if (blockIdx.x == 0) {
        float f0 = logit[tid], f1 = logit[tid + 256];
        float m = warpMax(fmaxf(f0, f1));
        if (lane == 0) s_red[wid] = m;
        __syncthreads();
        if (wid == 0) {
            float mm = (lane < 8) ? s_red[lane] : -1e30f;
            mm = warpMax(mm);
            if (lane == 0) s_m = mm;
        }
        __syncthreads();
        float m_all = s_m;
        int w0 = min(__float2int_rn(expf(f0 - m_all) * 127.f), 127);
        int w1 = min(__float2int_rn(expf(f1 - m_all) * 127.f), 127);
        vq[tid]       = (unsigned char)w0;
        vq[tid + 256] = (unsigned char)w1;
        float sw = warpSum((float)(w0 + w1));
        if (lane == 0) s_red[wid] = sw;
        __syncthreads();
        if (wid == 0) {
            float s = (lane < 8) ? s_red[lane] : 0.f;
            s = warpSum(s);
            if (lane == 0) s_s0 = s;
        }
        __syncthreads();
        if (wid == 0) {
            sw_reg = s_s0;
            if (lane == 0) accr = m_all - logf(127.f) + logf(s_s0);
        }
        __syncthreads();
    }

    const uint4* __restrict__ A4 = reinterpret_cast<const uint4*>(g_A);
    int jl[4];
    float rl[4], rh[4];
#pragma unroll
    for (int mi = 0; mi < 4; ++mi) {
        jl[mi] = (wid * 4 + mi) * 16 + gid;
        rl[mi] = s_rs[jl[mi]];
        rh[mi] = s_rs[jl[mi] + 8];
    }
    const int steps = BURN + K;

    for (int s = 0; s < steps; ++s) {
        // ---- prefetch logit for this step ----
        float fv[2][8];
        bool  act[2];
#pragma unroll
        for (int q = 0; q < 2; ++q) {
            int t = t0_e[q] + s;
            act[q] = (t < tend_e[q]);
            if (act[q]) {
                const float* lt = logit + ((long)t << 9);
#pragma unroll
                for (int mi = 0; mi < 4; ++mi) {
                    fv[q][mi * 2]     = lt[jl[mi]];
                    fv[q][mi * 2 + 1] = lt[jl[mi] + 8];
                }
            }
        }

        // ---- GEMM: D[512, 8] = E(s8) @ state(s8); this warp: 4 mtiles ----
        int d[4][4];
#pragma unroll
        for (int mi = 0; mi < 4; ++mi)
#pragma unroll
            for (int r = 0; r < 4; ++r) d[mi][r] = 0;

#pragma unroll
        for (int kc = 0; kc < 16; ++kc) {
            const int kb = kc * 32 + tig * 4;
            unsigned b0 = *reinterpret_cast<const unsigned*>(&vq[gid * VPITCH + kb]);
            unsigned b1 = *reinterpret_cast<const unsigned*>(&vq[gid * VPITCH + kb + 16]);
            uint4 A0 = A4[((wid * 4 + 0) * 16 + kc) * 32 + lane];
            uint4 A1 = A4[((wid * 4 + 1) * 16 + kc) * 32 + lane];
            uint4 A2 = A4[((wid * 4 + 2) * 16 + kc) * 32 + lane];
            uint4 A3 = A4[((wid * 4 + 3) * 16 + kc) * 32 + lane];
            imma(d[0][0], d[0][1], d[0][2], d[0][3], A0.x, A0.y, A0.z, A0.w, b0, b1);
            imma(d[1][0], d[1][1], d[1][2], d[1][3], A1.x, A1.y, A1.z, A1.w, b0, b1);
            imma(d[2][0], d[2][1], d[2][2], d[2][3], A2.x, A2.y, A2.z, A2.w, b0, b1);
            imma(d[3][0], d[3][1], d[3][2], d[3][3], A3.x, A3.y, A3.z, A3.w, b0, b1);
        }

        // ---- epilogue: z = exp(f) * rs_j * y  (cols: 2tig+q) ----
#pragma unroll
        for (int q = 0; q < 2; ++q) {
            if (act[q]) {
                float* zr = zbuf + (2 * tig + q) * ZP;
#pragma unroll
                for (int mi = 0; mi < 4; ++mi) {
                    zr[jl[mi]]     = __expf(fv[q][mi * 2])     * rl[mi] * (float)d[mi][q];
                    zr[jl[mi] + 8] = __expf(fv[q][mi * 2 + 1]) * rh[mi] * (float)d[mi][q + 2];
                }
            }
        }
        __syncthreads();

        // ---- warp wid: reduce + requant chain wid (warp-local) ----
        {
            int t = t0_w + s;
            if (t < tend_w) {
                float mx = -1e30f, sm = 0.f;
                const float* zr = zbuf + wid * ZP;
#pragma unroll
                for (int k = 0; k < 16; ++k) {
                    float z = zr[lane + 32 * k];
                    mx = fmaxf(mx, z);
                    sm += z;
                }
                mx = warpMax(mx);
                sm = warpSum(sm);
                float bcv = 127.f / mx;

                const float4* zb = reinterpret_cast<const float4*>(zr + lane * 16);
                unsigned pk[4];
                int lsum = 0;
#pragma unroll
                for (int p = 0; p < 4; ++p) {
                    float4 z = zb[p];
                    int w0 = min(__float2int_rn(z.x * bcv), 127);
                    int w1 = min(__float2int_rn(z.y * bcv), 127);
                    int w2 = min(__float2int_rn(z.z * bcv), 127);
                    int w3 = min(__float2int_rn(z.w * bcv), 127);
                    lsum += w0 + w1 + w2 + w3;
                    pk[p] = (unsigned)w0 | ((unsigned)w1 << 8) |
                            ((unsigned)w2 << 16) | ((unsigned)w3 << 24);
                }
                *reinterpret_cast<uint4*>(&vq[wid * VPITCH + lane * 16]) =
                    make_uint4(pk[0], pk[1], pk[2], pk[3]);
                unsigned tot = __reduce_add_sync(0xffffffffu, (unsigned)lsum);
                if (lane == 0 && t >= own_w) accr += logf(sm) - logf(sw_reg);
                sw_reg = (float)tot;
            }
        }
        __syncthreads();
    }

    if (lane == 0) g_acc[cg_w] = accr;
}

// ---------------------------------------------------------------------------
// Gold path score (parallel partials, deterministic).
// ---------------------------------------------------------------------------
__global__ void gold_kernel(const float* __restrict__ logit,
                            const int*   __restrict__ labels,
                            const float* __restrict__ T, int S) {
    __shared__ float red[8];
    const int tid = threadIdx.x;                 // 256
    float p = 0.f;
    for (int t = blockIdx.x * 256 + tid; t < S; t += GOLD_BLOCKS * 256) {
        int lt = labels[t];
        p += logit[(t << 9) + lt];
        if (t >= 1) p += T[(lt << 9) + labels[t - 1]];
    }
    p = warpSum(p);
    if ((tid & 31) == 0) red[tid >> 5] = p;
    __syncthreads();
    if (tid < 32) {
        float s = (tid < 8) ? red[tid] : 0.f;
        s = warpSum(s);
        if (tid == 0) g_gold_part[blockIdx.x] = s;
    }
}

// ---------------------------------------------------------------------------
// Final: 256-thread deterministic fixed-order double tree.
// ---------------------------------------------------------------------------
__global__ void final_kernel(float* __restrict__ out) {
    __shared__ double sd[256];
    const int tid = threadIdx.x;
    double v = 0.0;
    for (int c = tid; c < NCHUNK; c += 256) v += (double)g_acc[c];
    for (int b = tid; b < GOLD_BLOCKS; b += 256) v -= (double)g_gold_part[b];
    sd[tid] = v;
    __syncthreads();
    for (int o = 128; o; o >>= 1) {
        if (tid < o) sd[tid] += sd[tid + o];
        __syncthreads();
    }
    if (tid == 0) out[0] = (float)sd[0];
}

// ---------------------------------------------------------------------------
extern "C" void kernel_launch(void* const* d_in, const int* in_sizes, int n_in,
                              void* d_out, int out_size) {
    const float* logit  = (const float*)d_in[0];
    const int*   labels = (const int*)d_in[1];
    const float* T      = (const float*)d_in[2];
    const int S = in_sizes[1];                        // 32768
    const int K = (S - 1 + NCHUNK - 1) / NCHUNK;      // 14

    prep_rowmax<<<LNUM, 128>>>(T);
    prep_quant<<<(LNUM * LNUM + 255) / 256, 256>>>(T);
    gold_kernel<<<GOLD_BLOCKS, 256>>>(logit, labels, T, S);
    chunk_kernel<<<NCTA, 256>>>(logit, S, K);
    final_kernel<<<1, 256>>>((float*)d_out);
}

// round 10
// speedup vs baseline: 12.0692x; 1.0404x over previous
#include <cuda_runtime.h>

// CRF forward (log-partition) minus gold-path score — IMMA edition, v3.
//
// Exp-domain chunked chains: u_t = diag(exp(feat_t)) * E * u_{t-1}.
// E = exp(T) quantized per-row to s8 (0..127); state requantized to s8 each
// step; per-step log-growth telescoped exactly for the quantized shadow chain.
//
// v3 vs v2: 2 CTAs per SM (256 threads / 8 warps / 8 chains each) so one
// CTA's epilogue+barriers hide under the other's tensor work; every warp owns
// a chain in the epilogue (no idle half). BURN 12->6 (rel_err was bit-identical
// from 24->12; quantization dominates). Total chain-steps unchanged (47.4K) —
// the gain is tensor-pipe utilization 74% -> ~90%.

#define LNUM  512
#define NCTA  296                 // 2 per SM
#define NCH   8                   // chains per CTA (one n8 MMA group)
#define NCHUNK (NCTA * NCH)       // 2368
#define BURN  6
#define GOLD_BLOCKS 64
#define VPITCH 528                // vq row pitch (B-fragment reads conflict-free)
#define ZP     516                // zbuf row pitch (epilogue scatter conflict-free)

// Device scratch (static; no allocation allowed).
__device__ __align__(16) unsigned char g_A[LNUM * LNUM];  // E s8, A-fragment order
__device__ float g_rs[LNUM];
__device__ float g_rowmax[LNUM];
__device__ float g_acc[NCHUNK];
__device__ float g_gold_part[GOLD_BLOCKS];

// ---------------------------------------------------------------------------
__device__ __forceinline__ float warpSum(float x) {
#pragma unroll
    for (int o = 16; o; o >>= 1) x += __shfl_xor_sync(0xffffffffu, x, o);
    return x;
}
__device__ __forceinline__ float warpMax(float x) {
#pragma unroll
    for (int o = 16; o; o >>= 1) x = fmaxf(x, __shfl_xor_sync(0xffffffffu, x, o));
    return x;
}

__device__ __forceinline__ void imma(int& d0, int& d1, int& d2, int& d3,
                                     unsigned a0, unsigned a1, unsigned a2, unsigned a3,
                                     unsigned b0, unsigned b1) {
    asm volatile(
        "mma.sync.aligned.m16n8k32.row.col.s32.s8.s8.s32 "
        "{%0,%1,%2,%3},{%4,%5,%6,%7},{%8,%9},{%0,%1,%2,%3};"
        : "+r"(d0), "+r"(d1), "+r"(d2), "+r"(d3)
        : "r"(a0), "r"(a1), "r"(a2), "r"(a3), "r"(b0), "r"(b1));
}

// ---------------------------------------------------------------------------
// Prep 1: per-row max of T -> row scale rs_j = exp(maxT_j)/127.
// ---------------------------------------------------------------------------
__global__ void prep_rowmax(const float* __restrict__ T) {
    __shared__ float red[4];
    const int jrow = blockIdx.x;
    const int tid  = threadIdx.x;          // 128
    float m = -1e30f;
    for (int i = tid; i < LNUM; i += 128) m = fmaxf(m, T[jrow * LNUM + i]);
    m = warpMax(m);
    if ((tid & 31) == 0) red[tid >> 5] = m;
    __syncthreads();
    if (tid == 0) {
        float mm = fmaxf(fmaxf(red[0], red[1]), fmaxf(red[2], red[3]));
        g_rowmax[jrow] = mm;
        g_rs[jrow] = expf(mm) / 127.f;
    }
}

// ---------------------------------------------------------------------------
// Prep 2: Q[j,k] = round(exp(T[j,k]-maxT_j)*127), scattered into the exact
// mma.m16n8k32 A-fragment layout (verified in R6/R7):
//   byte = (((m*16+kc)*32 + gid*4+tig)*4 + (rhalf+2*khalf))*4 + (kk&3)
// ---------------------------------------------------------------------------
__global__ void prep_quant(const float* __restrict__ T) {
    int idx = blockIdx.x * blockDim.x + threadIdx.x;   // j*512 + k
    if (idx >= LNUM * LNUM) return;
    int j = idx >> 9;
    int k = idx & (LNUM - 1);
    float q = expf(T[idx] - g_rowmax[j]) * 127.f;
    int wi = min(__float2int_rn(q), 127);

    int m = j >> 4, r = j & 15, gid = r & 7, rh = r >> 3;
    int kc = k >> 5, kk = k & 31, tig = (kk >> 2) & 3, kh = kk >> 4, b = kk & 3;
    g_A[(((m * 16 + kc) * 32 + gid * 4 + tig) * 4 + (rh + 2 * kh)) * 4 + b] =
        (unsigned char)wi;
}

// ---------------------------------------------------------------------------
// Main: one CTA = 8 chains, 256 threads = 8 warps, 2 CTAs per SM.
// GEMM: warp w owns mtiles {4w..4w+3}. Epilogue: warp w owns chain w.
// ---------------------------------------------------------------------------
__global__ void __launch_bounds__(256, 2)
chunk_kernel(const float* __restrict__ logit, int S, int K) {
    __shared__ __align__(16) unsigned char vq[NCH * VPITCH];  // state, s8
    __shared__ __align__(16) float zbuf[NCH * ZP];
    __shared__ float s_rs[LNUM];
    __shared__ float s_red[8];
    __shared__ float s_m, s_s0;

    const int tid  = threadIdx.x;
    const int wid  = tid >> 5;          // 0..7
    const int lane = tid & 31;
    const int gid  = lane >> 2;
    const int tig  = lane & 3;

    s_rs[tid]       = g_rs[tid];
    s_rs[tid + 256] = g_rs[tid + 256];

    // --- warp-as-chain schedule (chain wid) ---
    const int cg_w   = blockIdx.x * NCH + wid;
    const int own_w  = 1 + cg_w * K;
    const int tend_w = min(own_w + K, S);
    const int t0_w   = (cg_w == 0) ? 1 : own_w - BURN;

    // --- epilogue chains for this thread: c = 2*tig + q ---
    int t0_e[2], tend_e[2];
#pragma unroll
    for (int q = 0; q < 2; ++q) {
        int cg = blockIdx.x * NCH + 2 * tig + q;
        int ow = 1 + cg * K;
        tend_e[q] = min(ow + K, S);
        t0_e[q]   = (cg == 0) ? 1 : ow - BURN;
    }

    // --- init: uniform state everywhere ---
#pragma unroll
    for (int c = 0; c < NCH; ++c) {
        vq[c * VPITCH + tid]       = 127;
        vq[c * VPITCH + tid + 256] = 127;
    }
    __syncthreads();

    float sw_reg = 127.f * (float)LNUM;   // sum of incoming state (exact int)
    float accr   = 0.f;                   // live in lane 0 of warp wid

    // --- chain 0 exact start from exp(feat_0) (block 0 only) ---
    if (blockIdx.x == 0) {
        float f0 = logit[tid], f1 = logit[tid + 256];
        float m = warpMax(fmaxf(f0, f1));
        if (lane == 0) s_red[wid] = m;
        __syncthreads();
        if (wid == 0) {
            float mm = (lane < 8) ? s_red[lane] : -1e30f;
            mm = warpMax(mm);
            if (lane == 0) s_m = mm;
        }
        __syncthreads();
        float m_all = s_m;
        int w0 = min(__float2int_rn(expf(f0 - m_all) * 127.f), 127);
        int w1 = min(__float2int_rn(expf(f1 - m_all) * 127.f), 127);
        vq[tid]       = (unsigned char)w0;
        vq[tid + 256] = (unsigned char)w1;
        float sw = warpSum((float)(w0 + w1));
        if (lane == 0) s_red[wid] = sw;
        __syncthreads();
        if (wid == 0) {
            float s = (lane < 8) ? s_red[lane] : 0.f;
            s = warpSum(s);
            if (lane == 0) s_s0 = s;
        }
        __syncthreads();
        if (wid == 0) {
            sw_reg = s_s0;
            if (lane == 0) accr = m_all - logf(127.f) + logf(s_s0);
        }
        __syncthreads();
    }

    const uint4* __restrict__ A4 = reinterpret_cast<const uint4*>(g_A);
    int jl[4];
    float rl[4], rh[4];
#pragma unroll
    for (int mi = 0; mi < 4; ++mi) {
        jl[mi] = (wid * 4 + mi) * 16 + gid;
        rl[mi] = s_rs[jl[mi]];
        rh[mi] = s_rs[jl[mi] + 8];
    }
    const int steps = BURN + K;

    for (int s = 0; s < steps; ++s) {
        // ---- prefetch logit for this step ----
        float fv[2][8];
        bool  act[2];
#pragma unroll
        for (int q = 0; q < 2; ++q) {
            int t = t0_e[q] + s;
            act[q] = (t < tend_e[q]);
            if (act[q]) {
                const float* lt = logit + ((long)t << 9);
#pragma unroll
                for (int mi = 0; mi < 4; ++mi) {
                    fv[q][mi * 2]     = lt[jl[mi]];
                    fv[q][mi * 2 + 1] = lt[jl[mi] + 8];
                }
            }
        }

        // ---- GEMM: D[512, 8] = E(s8) @ state(s8); this warp: 4 mtiles ----
        int d[4][4];
#pragma unroll
        for (int mi = 0; mi < 4; ++mi)
#pragma unroll
            for (int r = 0; r < 4; ++r) d[mi][r] = 0;

#pragma unroll
        for (int kc = 0; kc < 16; ++kc) {
            const int kb = kc * 32 + tig * 4;
            unsigned b0 = *reinterpret_cast<const unsigned*>(&vq[gid * VPITCH + kb]);
            unsigned b1 = *reinterpret_cast<const unsigned*>(&vq[gid * VPITCH + kb + 16]);
            uint4 A0 = A4[((wid * 4 + 0) * 16 + kc) * 32 + lane];
            uint4 A1 = A4[((wid * 4 + 1) * 16 + kc) * 32 + lane];
            uint4 A2 = A4[((wid * 4 + 2) * 16 + kc) * 32 + lane];
            uint4 A3 = A4[((wid * 4 + 3) * 16 + kc) * 32 + lane];
            imma(d[0][0], d[0][1], d[0][2], d[0][3], A0.x, A0.y, A0.z, A0.w, b0, b1);
            imma(d[1][0], d[1][1], d[1][2], d[1][3], A1.x, A1.y, A1.z, A1.w, b0, b1);
            imma(d[2][0], d[2][1], d[2][2], d[2][3], A2.x, A2.y, A2.z, A2.w, b0, b1);
            imma(d[3][0], d[3][1], d[3][2], d[3][3], A3.x, A3.y, A3.z, A3.w, b0, b1);
        }

        // ---- epilogue: z = exp(f) * rs_j * y  (cols: 2tig+q) ----
#pragma unroll
        for (int q = 0; q < 2; ++q) {
            if (act[q]) {
                float* zr = zbuf + (2 * tig + q) * ZP;
#pragma unroll
                for (int mi = 0; mi < 4; ++mi) {
                    zr[jl[mi]]     = __expf(fv[q][mi * 2])     * rl[mi] * (float)d[mi][q];
                    zr[jl[mi] + 8] = __expf(fv[q][mi * 2 + 1]) * rh[mi] * (float)d[mi][q + 2];
                }
            }
        }
        __syncthreads();

        // ---- warp wid: reduce + requant chain wid (warp-local) ----
        {
            int t = t0_w + s;
            if (t < tend_w) {
                float mx = -1e30f, sm = 0.f;
                const float* zr = zbuf + wid * ZP;
#pragma unroll
                for (int k = 0; k < 16; ++k) {
                    float z = zr[lane + 32 * k];
                    mx = fmaxf(mx, z);
                    sm += z;
                }
                mx = warpMax(mx);
                sm = warpSum(sm);
                float bcv = 127.f / mx;

                const float4* zb = reinterpret_cast<const float4*>(zr + lane * 16);
                unsigned pk[4];
                int lsum = 0;
#pragma unroll
                for (int p = 0; p < 4; ++p) {
                    float4 z = zb[p];
                    int w0 = min(__float2int_rn(z.x * bcv), 127);
                    int w1 = min(__float2int_rn(z.y * bcv), 127);
                    int w2 = min(__float2int_rn(z.z * bcv), 127);
                    int w3 = min(__float2int_rn(z.w * bcv), 127);
                    lsum += w0 + w1 + w2 + w3;
                    pk[p] = (unsigned)w0 | ((unsigned)w1 << 8) |
                            ((unsigned)w2 << 16) | ((unsigned)w3 << 24);
                }
                *reinterpret_cast<uint4*>(&vq[wid * VPITCH + lane * 16]) =
                    make_uint4(pk[0], pk[1], pk[2], pk[3]);
                unsigned tot = __reduce_add_sync(0xffffffffu, (unsigned)lsum);
                if (lane == 0 && t >= own_w) accr += logf(sm) - logf(sw_reg);
                sw_reg = (float)tot;
            }
        }
        __syncthreads();
    }

    if (lane == 0) g_acc[cg_w] = accr;
}

// ---------------------------------------------------------------------------
// Gold path score (parallel partials, deterministic).
// ---------------------------------------------------------------------------
__global__ void gold_kernel(const float* __restrict__ logit,
                            const int*   __restrict__ labels,
                            const float* __restrict__ T, int S) {
    __shared__ float red[8];
    const int tid = threadIdx.x;                 // 256
    float p = 0.f;
    for (int t = blockIdx.x * 256 + tid; t < S; t += GOLD_BLOCKS * 256) {
        int lt = labels[t];
        p += logit[(t << 9) + lt];
        if (t >= 1) p += T[(lt << 9) + labels[t - 1]];
    }
    p = warpSum(p);
    if ((tid & 31) == 0) red[tid >> 5] = p;
    __syncthreads();
    if (tid < 32) {
        float s = (tid < 8) ? red[tid] : 0.f;
        s = warpSum(s);
        if (tid == 0) g_gold_part[blockIdx.x] = s;
    }
}

// ---------------------------------------------------------------------------
// Final: 256-thread deterministic fixed-order double tree.
// ---------------------------------------------------------------------------
__global__ void final_kernel(float* __restrict__ out) {
    __shared__ double sd[256];
    const int tid = threadIdx.x;
    double v = 0.0;
    for (int c = tid; c < NCHUNK; c += 256) v += (double)g_acc[c];
    for (int b = tid; b < GOLD_BLOCKS; b += 256) v -= (double)g_gold_part[b];
    sd[tid] = v;
    __syncthreads();
    for (int o = 128; o; o >>= 1) {
        if (tid < o) sd[tid] += sd[tid + o];
        __syncthreads();
    }
    if (tid == 0) out[0] = (float)sd[0];
}

// ---------------------------------------------------------------------------
extern "C" void kernel_launch(void* const* d_in, const int* in_sizes, int n_in,
                              void* d_out, int out_size) {
    const float* logit  = (const float*)d_in[0];
    const int*   labels = (const int*)d_in[1];
    const float* T      = (const float*)d_in[2];
    const int S = in_sizes[1];                        // 32768
    const int K = (S - 1 + NCHUNK - 1) / NCHUNK;      // 14

    prep_rowmax<<<LNUM, 128>>>(T);
    prep_quant<<<(LNUM * LNUM + 255) / 256, 256>>>(T);
    gold_kernel<<<GOLD_BLOCKS, 256>>>(logit, labels, T, S);
    chunk_kernel<<<NCTA, 256>>>(logit, S, K);
    final_kernel<<<1, 256>>>((float*)d_out);
}

// round 11
// speedup vs baseline: 14.0105x; 1.1608x over previous
#include <cuda_runtime.h>

// CRF forward (log-partition) minus gold-path score — IMMA edition, v4.
//
// Exp-domain chunked chains: u_t = diag(exp(feat_t)) * E * u_{t-1}.
// E = exp(T) quantized per-row to s8 (0..127); state requantized to s8 each
// step; per-step log-growth telescoped exactly for the quantized shadow chain.
//
// v4 vs v3: BURN 6->3 (rel_err bit-identical across 24->12->6 bounds the
// contraction at c<=0.35; worst-case added error at BURN=3 is ~2e-5 rel,
// 25x under threshold). Chain-steps 46975 -> 39871 (0.849x). prep_quant
// packs 4 bytes per store (fragment-word contiguous).

#define LNUM  512
#define NCTA  296                 // 2 per SM
#define NCH   8                   // chains per CTA (one n8 MMA group)
#define NCHUNK (NCTA * NCH)       // 2368
#define BURN  3
#define GOLD_BLOCKS 64
#define VPITCH 528                // vq row pitch (B-fragment reads conflict-free)
#define ZP     516                // zbuf row pitch (epilogue scatter conflict-free)

// Device scratch (static; no allocation allowed).
__device__ __align__(16) unsigned char g_A[LNUM * LNUM];  // E s8, A-fragment order
__device__ float g_rs[LNUM];
__device__ float g_rowmax[LNUM];
__device__ float g_acc[NCHUNK];
__device__ float g_gold_part[GOLD_BLOCKS];

// ---------------------------------------------------------------------------
__device__ __forceinline__ float warpSum(float x) {
#pragma unroll
    for (int o = 16; o; o >>= 1) x += __shfl_xor_sync(0xffffffffu, x, o);
    return x;
}
__device__ __forceinline__ float warpMax(float x) {
#pragma unroll
    for (int o = 16; o; o >>= 1) x = fmaxf(x, __shfl_xor_sync(0xffffffffu, x, o));
    return x;
}

__device__ __forceinline__ void imma(int& d0, int& d1, int& d2, int& d3,
                                     unsigned a0, unsigned a1, unsigned a2, unsigned a3,
                                     unsigned b0, unsigned b1) {
    asm volatile(
        "mma.sync.aligned.m16n8k32.row.col.s32.s8.s8.s32 "
        "{%0,%1,%2,%3},{%4,%5,%6,%7},{%8,%9},{%0,%1,%2,%3};"
        : "+r"(d0), "+r"(d1), "+r"(d2), "+r"(d3)
        : "r"(a0), "r"(a1), "r"(a2), "r"(a3), "r"(b0), "r"(b1));
}

// ---------------------------------------------------------------------------
// Prep 1: per-row max of T -> row scale rs_j = exp(maxT_j)/127.
// ---------------------------------------------------------------------------
__global__ void prep_rowmax(const float* __restrict__ T) {
    __shared__ float red[4];
    const int jrow = blockIdx.x;
    const int tid  = threadIdx.x;          // 128
    float m = -1e30f;
    for (int i = tid; i < LNUM; i += 128) m = fmaxf(m, T[jrow * LNUM + i]);
    m = warpMax(m);
    if ((tid & 31) == 0) red[tid >> 5] = m;
    __syncthreads();
    if (tid == 0) {
        float mm = fmaxf(fmaxf(red[0], red[1]), fmaxf(red[2], red[3]));
        g_rowmax[jrow] = mm;
        g_rs[jrow] = expf(mm) / 127.f;
    }
}

// ---------------------------------------------------------------------------
// Prep 2: Q[j,k] = round(exp(T[j,k]-maxT_j)*127) scattered into the exact
// mma.m16n8k32 A-fragment layout (verified R6-R10). One thread handles 4
// consecutive k (the 4 bytes of one fragment word) -> single u32 store:
//   word = ((m*16+kc)*32 + gid*4 + tig)*4 + (rhalf + 2*khalf)
// ---------------------------------------------------------------------------
__global__ void prep_quant(const float* __restrict__ T) {
    int idx4 = blockIdx.x * blockDim.x + threadIdx.x;  // j*128 + k4
    if (idx4 >= LNUM * LNUM / 4) return;
    int j  = idx4 >> 7;
    int k4 = idx4 & 127;
    float mx = g_rowmax[j];
    const float* tr = T + j * LNUM + k4 * 4;
    unsigned w = 0;
#pragma unroll
    for (int b = 0; b < 4; ++b) {
        int q = min(__float2int_rn(expf(tr[b] - mx) * 127.f), 127);
        w |= (unsigned)q << (8 * b);
    }
    int m = j >> 4, r = j & 15, gid = r & 7, rh = r >> 3;
    int kc = k4 >> 3, tig = k4 & 7 & 3, kh = (k4 >> 2) & 1;
    tig = (k4 & 7) >> 0 & 3;      // tig = (kk>>2)&3 with kk=4*k4+b -> k4&3? no:
    // kk>>2 = k4 (within 0..7 mod), precisely tig = k4 & 3 when k4&7 < 4 else (k4&7)-4?
    // Derivation: kk = k4*4 + b, kk&31 = (k4&7)*4 + b, (kk&31)>>2 = k4&7 -> tig = (k4&7)&3, kh = (k4&7)>>2
    tig = (k4 & 7) & 3;
    kh  = (k4 & 7) >> 2;
    reinterpret_cast<unsigned*>(g_A)[((m * 16 + kc) * 32 + gid * 4 + tig) * 4 +
                                     (rh + 2 * kh)] = w;
}

// ---------------------------------------------------------------------------
// Main: one CTA = 8 chains, 256 threads = 8 warps, 2 CTAs per SM.
// GEMM: warp w owns mtiles {4w..4w+3}. Epilogue: warp w owns chain w.
// ---------------------------------------------------------------------------
__global__ void __launch_bounds__(256, 2)
chunk_kernel(const float* __restrict__ logit, int S, int K) {
    __shared__ __align__(16) unsigned char vq[NCH * VPITCH];  // state, s8
    __shared__ __align__(16) float zbuf[NCH * ZP];
    __shared__ float s_rs[LNUM];
    __shared__ float s_red[8];
    __shared__ float s_m, s_s0;

    const int tid  = threadIdx.x;
    const int wid  = tid >> 5;          // 0..7
    const int lane = tid & 31;
    const int gid  = lane >> 2;
    const int tig  = lane & 3;

    s_rs[tid]       = g_rs[tid];
    s_rs[tid + 256] = g_rs[tid + 256];

    // --- warp-as-chain schedule (chain wid) ---
    const int cg_w   = blockIdx.x * NCH + wid;
    const int own_w  = 1 + cg_w * K;
    const int tend_w = min(own_w + K, S);
    const int t0_w   = (cg_w == 0) ? 1 : own_w - BURN;

    // --- epilogue chains for this thread: c = 2*tig + q ---
    int t0_e[2], tend_e[2];
#pragma unroll
    for (int q = 0; q < 2; ++q) {
        int cg = blockIdx.x * NCH + 2 * tig + q;
        int ow = 1 + cg * K;
        tend_e[q] = min(ow + K, S);
        t0_e[q]   = (cg == 0) ? 1 : ow - BURN;
    }

    // --- init: uniform state everywhere ---
#pragma unroll
    for (int c = 0; c < NCH; ++c) {
        vq[c * VPITCH + tid]       = 127;
        vq[c * VPITCH + tid + 256] = 127;
    }
    __syncthreads();

    float sw_reg = 127.f * (float)LNUM;   // sum of incoming state (exact int)
    float accr   = 0.f;                   // live in lane 0 of warp wid

    // --- chain 0 exact start from exp(feat_0) (block 0 only) ---
    if (blockIdx.x == 0) {
        float f0 = logit[tid], f1 = logit[tid + 256];
        float m = warpMax(fmaxf(f0, f1));
        if (lane == 0) s_red[wid] = m;
        __syncthreads();
        if (wid == 0) {
            float mm = (lane < 8) ? s_red[lane] : -1e30f;
            mm = warpMax(mm);
            if (lane == 0) s_m = mm;
        }
        __syncthreads();
        float m_all = s_m;
        int w0 = min(__float2int_rn(expf(f0 - m_all) * 127.f), 127);
        int w1 = min(__float2int_rn(expf(f1 - m_all) * 127.f), 127);
        vq[tid]       = (unsigned char)w0;
        vq[tid + 256] = (unsigned char)w1;
        float sw = warpSum((float)(w0 + w1));
        if (lane == 0) s_red[wid] = sw;
        __syncthreads();
        if (wid == 0) {
            float s = (lane < 8) ? s_red[lane] : 0.f;
            s = warpSum(s);
            if (lane == 0) s_s0 = s;
        }
        __syncthreads();
        if (wid == 0) {
            sw_reg = s_s0;
            if (lane == 0) accr = m_all - logf(127.f) + logf(s_s0);
        }
        __syncthreads();
    }

    const uint4* __restrict__ A4 = reinterpret_cast<const uint4*>(g_A);
    int jl[4];
    float rl[4], rh[4];
#pragma unroll
    for (int mi = 0; mi < 4; ++mi) {
        jl[mi] = (wid * 4 + mi) * 16 + gid;
        rl[mi] = s_rs[jl[mi]];
        rh[mi] = s_rs[jl[mi] + 8];
    }
    const int steps = BURN + K;

    for (int s = 0; s < steps; ++s) {
        // ---- prefetch logit for this step ----
        float fv[2][8];
        bool  act[2];
#pragma unroll
        for (int q = 0; q < 2; ++q) {
            int t = t0_e[q] + s;
            act[q] = (t < tend_e[q]);
            if (act[q]) {
                const float* lt = logit + ((long)t << 9);
#pragma unroll
                for (int mi = 0; mi < 4; ++mi) {
                    fv[q][mi * 2]     = lt[jl[mi]];
                    fv[q][mi * 2 + 1] = lt[jl[mi] + 8];
                }
            }
        }

        // ---- GEMM: D[512, 8] = E(s8) @ state(s8); this warp: 4 mtiles ----
        int d[4][4];
#pragma unroll
        for (int mi = 0; mi < 4; ++mi)
#pragma unroll
            for (int r = 0; r < 4; ++r) d[mi][r] = 0;

#pragma unroll
        for (int kc = 0; kc < 16; ++kc) {
            const int kb = kc * 32 + tig * 4;
            unsigned b0 = *reinterpret_cast<const unsigned*>(&vq[gid * VPITCH + kb]);
            unsigned b1 = *reinterpret_cast<const unsigned*>(&vq[gid * VPITCH + kb + 16]);
            uint4 A0 = A4[((wid * 4 + 0) * 16 + kc) * 32 + lane];
            uint4 A1 = A4[((wid * 4 + 1) * 16 + kc) * 32 + lane];
            uint4 A2 = A4[((wid * 4 + 2) * 16 + kc) * 32 + lane];
            uint4 A3 = A4[((wid * 4 + 3) * 16 + kc) * 32 + lane];
            imma(d[0][0], d[0][1], d[0][2], d[0][3], A0.x, A0.y, A0.z, A0.w, b0, b1);
            imma(d[1][0], d[1][1], d[1][2], d[1][3], A1.x, A1.y, A1.z, A1.w, b0, b1);
            imma(d[2][0], d[2][1], d[2][2], d[2][3], A2.x, A2.y, A2.z, A2.w, b0, b1);
            imma(d[3][0], d[3][1], d[3][2], d[3][3], A3.x, A3.y, A3.z, A3.w, b0, b1);
        }

        // ---- epilogue: z = exp(f) * rs_j * y  (cols: 2tig+q) ----
#pragma unroll
        for (int q = 0; q < 2; ++q) {
            if (act[q]) {
                float* zr = zbuf + (2 * tig + q) * ZP;
#pragma unroll
                for (int mi = 0; mi < 4; ++mi) {
                    zr[jl[mi]]     = __expf(fv[q][mi * 2])     * rl[mi] * (float)d[mi][q];
                    zr[jl[mi] + 8] = __expf(fv[q][mi * 2 + 1]) * rh[mi] * (float)d[mi][q + 2];
                }
            }
        }
        __syncthreads();

        // ---- warp wid: reduce + requant chain wid (warp-local) ----
        {
            int t = t0_w + s;
            if (t < tend_w) {
                float mx = -1e30f, sm = 0.f;
                const float* zr = zbuf + wid * ZP;
#pragma unroll
                for (int k = 0; k < 16; ++k) {
                    float z = zr[lane + 32 * k];
                    mx = fmaxf(mx, z);
                    sm += z;
                }
                mx = warpMax(mx);
                sm = warpSum(sm);
                float bcv = 127.f / mx;

                const float4* zb = reinterpret_cast<const float4*>(zr + lane * 16);
                unsigned pk[4];
                int lsum = 0;
#pragma unroll
                for (int p = 0; p < 4; ++p) {
                    float4 z = zb[p];
                    int w0 = min(__float2int_rn(z.x * bcv), 127);
                    int w1 = min(__float2int_rn(z.y * bcv), 127);
                    int w2 = min(__float2int_rn(z.z * bcv), 127);
                    int w3 = min(__float2int_rn(z.w * bcv), 127);
                    lsum += w0 + w1 + w2 + w3;
                    pk[p] = (unsigned)w0 | ((unsigned)w1 << 8) |
                            ((unsigned)w2 << 16) | ((unsigned)w3 << 24);
                }
                *reinterpret_cast<uint4*>(&vq[wid * VPITCH + lane * 16]) =
                    make_uint4(pk[0], pk[1], pk[2], pk[3]);
                unsigned tot = __reduce_add_sync(0xffffffffu, (unsigned)lsum);
                if (lane == 0 && t >= own_w) accr += logf(sm) - logf(sw_reg);
                sw_reg = (float)tot;
            }
        }
        __syncthreads();
    }

    if (lane == 0) g_acc[cg_w] = accr;
}

// ---------------------------------------------------------------------------
// Gold path score (parallel partials, deterministic).
// ---------------------------------------------------------------------------
__global__ void gold_kernel(const float* __restrict__ logit,
                            const int*   __restrict__ labels,
                            const float* __restrict__ T, int S) {
    __shared__ float red[8];
    const int tid = threadIdx.x;                 // 256
    float p = 0.f;
    for (int t = blockIdx.x * 256 + tid; t < S; t += GOLD_BLOCKS * 256) {
        int lt = labels[t];
        p += logit[(t << 9) + lt];
        if (t >= 1) p += T[(lt << 9) + labels[t - 1]];
    }
    p = warpSum(p);
    if ((tid & 31) == 0) red[tid >> 5] = p;
    __syncthreads();
    if (tid < 32) {
        float s = (tid < 8) ? red[tid] : 0.f;
        s = warpSum(s);
        if (tid == 0) g_gold_part[blockIdx.x] = s;
    }
}

// ---------------------------------------------------------------------------
// Final: 256-thread deterministic fixed-order double tree.
// ---------------------------------------------------------------------------
__global__ void final_kernel(float* __restrict__ out) {
    __shared__ double sd[256];
    const int tid = threadIdx.x;
    double v = 0.0;
    for (int c = tid; c < NCHUNK; c += 256) v += (double)g_acc[c];
    for (int b = tid; b < GOLD_BLOCKS; b += 256) v -= (double)g_gold_part[b];
    sd[tid] = v;
    __syncthreads();
    for (int o = 128; o; o >>= 1) {
        if (tid < o) sd[tid] += sd[tid + o];
        __syncthreads();
    }
    if (tid == 0) out[0] = (float)sd[0];
}

// ---------------------------------------------------------------------------
extern "C" void kernel_launch(void* const* d_in, const int* in_sizes, int n_in,
                              void* d_out, int out_size) {
    const float* logit  = (const float*)d_in[0];
    const int*   labels = (const int*)d_in[1];
    const float* T      = (const float*)d_in[2];
    const int S = in_sizes[1];                        // 32768
    const int K = (S - 1 + NCHUNK - 1) / NCHUNK;      // 14

    prep_rowmax<<<LNUM, 128>>>(T);
    prep_quant<<<(LNUM * LNUM / 4 + 255) / 256, 256>>>(T);
    gold_kernel<<<GOLD_BLOCKS, 256>>>(logit, labels, T, S);
    chunk_kernel<<<NCTA, 256>>>(logit, S, K);
    final_kernel<<<1, 256>>>((float*)d_out);
}